// round 7
// baseline (speedup 1.0000x reference)
#include <cuda_runtime.h>
#include <math_constants.h>

// ============================================================
// ChamferLoss via exact uniform-grid nearest neighbor.
// Grid G^3 over [-6,6]^3. Expanding Chebyshev-ring search with exact
// cube-face lower bound (faces at/past grid edge => +inf, so coordinate
// clamping stays exact). Queries run in grid-sorted order (coherent).
// Pipeline: zero -> histogram -> scan -> scatter -> query -> reduce x2.
// g_dist indexed by original point index => bit-deterministic output.
// ============================================================

#define G 64
#define NCELLS (G * G * G)
#define GRID_LO (-6.0f)
#define HCELL 0.1875f            // 12/64
#define INV_H (64.0f / 12.0f)
#define MAXPTS 16384
#define RED_CTAS 64
#define RED_THREADS 256

__device__ float4 g_sorted[2][MAXPTS];
__device__ int    g_start[2][NCELLS + 1];
__device__ int    g_cursor[2][NCELLS];   // counts during build, cursors during scatter
__device__ float  g_dist[2 * MAXPTS];
__device__ float  g_part[RED_CTAS];

__device__ __forceinline__ int cell_coord(float v) {
    int c = (int)((v - GRID_LO) * INV_H);
    return min(max(c, 0), G - 1);
}

// ---------- 1. zero cell counts ----------
__global__ void zero_kernel() {
    int i = blockIdx.x * 1024 + threadIdx.x;
    if (i < 2 * NCELLS) ((int*)g_cursor)[i] = 0;
}

// ---------- 2. histogram ----------
__global__ void build_kernel(const float* __restrict__ A,
                             const float* __restrict__ B, int N, int M) {
    int gid = blockIdx.x * blockDim.x + threadIdx.x;
    if (gid >= N + M) return;
    int cloud = (gid >= N);
    int i = cloud ? gid - N : gid;
    const float* src = cloud ? B : A;
    float x = src[3 * i], y = src[3 * i + 1], z = src[3 * i + 2];
    int cell = (cell_coord(z) * G + cell_coord(y)) * G + cell_coord(x);
    atomicAdd(&g_cursor[cloud][cell], 1);
}

// ---------- 3. exclusive prefix scan (one CTA per cloud) ----------
__global__ void __launch_bounds__(1024)
scan_kernel() {
    const int cloud = blockIdx.x;
    const int tid = threadIdx.x;
    const int CPT = NCELLS / 1024;        // 256 cells per thread
    __shared__ int ssum[1024];

    const int base = tid * CPT;
    int s = 0;
    #pragma unroll 8
    for (int c = 0; c < CPT; c++) s += g_cursor[cloud][base + c];
    ssum[tid] = s;
    __syncthreads();
    for (int off = 1; off < 1024; off <<= 1) {
        int v = (tid >= off) ? ssum[tid - off] : 0;
        __syncthreads();
        ssum[tid] += v;
        __syncthreads();
    }
    int run = ssum[tid] - s;              // exclusive prefix for this thread
    for (int c = 0; c < CPT; c++) {
        int cnt = g_cursor[cloud][base + c];
        g_start[cloud][base + c] = run;
        g_cursor[cloud][base + c] = run;  // scatter cursor
        run += cnt;
    }
    if (tid == 1023) g_start[cloud][NCELLS] = run;
}

// ---------- 4. scatter into grid-sorted order ----------
__global__ void scatter_kernel(const float* __restrict__ A,
                               const float* __restrict__ B, int N, int M) {
    int gid = blockIdx.x * blockDim.x + threadIdx.x;
    if (gid >= N + M) return;
    int cloud = (gid >= N);
    int i = cloud ? gid - N : gid;
    const float* src = cloud ? B : A;
    float x = src[3 * i], y = src[3 * i + 1], z = src[3 * i + 2];
    int cell = (cell_coord(z) * G + cell_coord(y)) * G + cell_coord(x);
    int pos = atomicAdd(&g_cursor[cloud][cell], 1);
    g_sorted[cloud][pos] = make_float4(x, y, z, __int_as_float(i));
}

// ---------- 5. expanding-ring NN query ----------
__device__ __forceinline__ void eval_range(const float4* __restrict__ pts,
                                           int s, int e,
                                           float qx, float qy, float qz,
                                           float& best) {
    #pragma unroll 4
    for (int k = s; k < e; k++) {
        float4 p = pts[k];
        float dx = qx - p.x, dy = qy - p.y, dz = qz - p.z;
        float d = fmaf(dx, dx, fmaf(dy, dy, dz * dz));
        best = fminf(best, d);
    }
}

__global__ void __launch_bounds__(128)
query_kernel(int N, int M) {
    int gid = blockIdx.x * blockDim.x + threadIdx.x;
    if (gid >= N + M) return;
    const int cq = (gid >= N);            // query cloud
    const int i = cq ? gid - N : gid;
    const int ct = 1 - cq;                // target cloud

    const float4 p = g_sorted[cq][i];
    const float qx = p.x, qy = p.y, qz = p.z;
    const int cx = cell_coord(qx), cy = cell_coord(qy), cz = cell_coord(qz);
    const int* __restrict__ start = g_start[ct];
    const float4* __restrict__ pts = g_sorted[ct];

    float best = CUDART_INF_F;
    for (int r = 0; r <= G; r++) {
        if (r > 0) {
            // lower bound on distance to anything outside scanned cube (radius r-1)
            const int rr = r - 1;
            float b = CUDART_INF_F;
            if (cx - rr > 0)     b = fminf(b, qx - (GRID_LO + (cx - rr) * HCELL));
            if (cx + rr < G - 1) b = fminf(b, (GRID_LO + (cx + rr + 1) * HCELL) - qx);
            if (cy - rr > 0)     b = fminf(b, qy - (GRID_LO + (cy - rr) * HCELL));
            if (cy + rr < G - 1) b = fminf(b, (GRID_LO + (cy + rr + 1) * HCELL) - qy);
            if (cz - rr > 0)     b = fminf(b, qz - (GRID_LO + (cz - rr) * HCELL));
            if (cz + rr < G - 1) b = fminf(b, (GRID_LO + (cz + rr + 1) * HCELL) - qz);
            if (best <= b * b) break;     // b==inf when whole grid scanned
        }
        // scan Chebyshev ring r
        const int zlo = max(cz - r, 0), zhi = min(cz + r, G - 1);
        for (int z = zlo; z <= zhi; z++) {
            const bool zf = (z == cz - r) || (z == cz + r);
            const int ylo = max(cy - r, 0), yhi = min(cy + r, G - 1);
            for (int y = ylo; y <= yhi; y++) {
                const bool yf = zf || (y == cy - r) || (y == cy + r);
                const int rowbase = (z * G + y) * G;
                if (yf) {
                    // full x-row: cells are x-contiguous -> one merged range
                    const int xlo = max(cx - r, 0), xhi = min(cx + r, G - 1);
                    eval_range(pts, start[rowbase + xlo], start[rowbase + xhi + 1],
                               qx, qy, qz, best);
                } else {
                    if (cx - r >= 0) {
                        const int c = rowbase + cx - r;
                        eval_range(pts, start[c], start[c + 1], qx, qy, qz, best);
                    }
                    if (cx + r <= G - 1) {
                        const int c = rowbase + cx + r;
                        eval_range(pts, start[c], start[c + 1], qx, qy, qz, best);
                    }
                }
            }
        }
    }

    const int orig = __float_as_int(p.w);
    g_dist[(cq ? N : 0) + orig] = sqrtf(best);
}

// ---------- 6-7. deterministic two-stage sum ----------
__global__ void __launch_bounds__(RED_THREADS)
reduce1_kernel(int total) {
    __shared__ float ssum[RED_THREADS / 32];
    const int per = (total + RED_CTAS - 1) / RED_CTAS;
    const int base = blockIdx.x * per;
    const int end = min(base + per, total);

    float acc = 0.0f;
    for (int i = base + threadIdx.x; i < end; i += RED_THREADS)
        acc += g_dist[i];
    #pragma unroll
    for (int o = 16; o > 0; o >>= 1)
        acc += __shfl_down_sync(0xFFFFFFFFu, acc, o);
    if ((threadIdx.x & 31) == 0) ssum[threadIdx.x >> 5] = acc;
    __syncthreads();
    if (threadIdx.x == 0) {
        float v = 0.0f;
        #pragma unroll
        for (int w = 0; w < RED_THREADS / 32; w++) v += ssum[w];
        g_part[blockIdx.x] = v;
    }
}

__global__ void reduce2_kernel(float* __restrict__ out) {
    float acc = 0.0f;
    #pragma unroll
    for (int k = 0; k < RED_CTAS / 32; k++)
        acc += g_part[threadIdx.x + 32 * k];
    #pragma unroll
    for (int o = 16; o > 0; o >>= 1)
        acc += __shfl_down_sync(0xFFFFFFFFu, acc, o);
    if (threadIdx.x == 0) out[0] = acc * 0.001f;
}

extern "C" void kernel_launch(void* const* d_in, const int* in_sizes, int n_in,
                              void* d_out, int out_size)
{
    const float* A = (const float*)d_in[0];   // target_pc [N,3]
    const float* B = (const float*)d_in[1];   // output_pc [M,3]
    const int N = in_sizes[0] / 3;
    const int M = in_sizes[1] / 3;
    const int total = N + M;

    zero_kernel<<<(2 * NCELLS + 1023) / 1024, 1024>>>();
    build_kernel<<<(total + 255) / 256, 256>>>(A, B, N, M);
    scan_kernel<<<2, 1024>>>();
    scatter_kernel<<<(total + 255) / 256, 256>>>(A, B, N, M);
    query_kernel<<<(total + 127) / 128, 128>>>(N, M);
    reduce1_kernel<<<RED_CTAS, RED_THREADS>>>(total);
    reduce2_kernel<<<1, 32>>>((float*)d_out);
}

// round 8
// speedup vs baseline: 4.7516x; 4.7516x over previous
#include <cuda_runtime.h>
#include <math_constants.h>

// ============================================================
// ChamferLoss via exact uniform-grid NN, WARP-COOPERATIVE queries.
// One warp per query: ring/bound control flow is warp-uniform (no
// divergence), candidate rows scanned lane-strided (coalesced float4).
// G=32 (h=0.375): rings 0-1 nearly always suffice; exactness from the
// cube-face lower bound (beyond-edge faces => +inf, so clamping is exact).
// Pipeline: zero -> histogram -> scan -> scatter -> query -> reduce x2.
// ============================================================

#define G 32
#define NCELLS (G * G * G)
#define GRID_LO (-6.0f)
#define HCELL 0.375f             // 12/32
#define INV_H (32.0f / 12.0f)
#define MAXPTS 16384
#define RED_CTAS 64
#define RED_THREADS 256

__device__ float4 g_sorted[2][MAXPTS];
__device__ int    g_start[2][NCELLS + 1];
__device__ int    g_cursor[2][NCELLS];   // counts during build, cursors in scatter
__device__ float  g_dist[2 * MAXPTS];
__device__ float  g_part[RED_CTAS];

__device__ __forceinline__ int cell_coord(float v) {
    int c = (int)((v - GRID_LO) * INV_H);
    return min(max(c, 0), G - 1);
}

// ---------- 1. zero cell counts ----------
__global__ void zero_kernel() {
    int i = blockIdx.x * 1024 + threadIdx.x;
    if (i < 2 * NCELLS) ((int*)g_cursor)[i] = 0;
}

// ---------- 2. histogram ----------
__global__ void build_kernel(const float* __restrict__ A,
                             const float* __restrict__ B, int N, int M) {
    int gid = blockIdx.x * blockDim.x + threadIdx.x;
    if (gid >= N + M) return;
    int cloud = (gid >= N);
    int i = cloud ? gid - N : gid;
    const float* src = cloud ? B : A;
    float x = src[3 * i], y = src[3 * i + 1], z = src[3 * i + 2];
    int cell = (cell_coord(z) * G + cell_coord(y)) * G + cell_coord(x);
    atomicAdd(&g_cursor[cloud][cell], 1);
}

// ---------- 3. exclusive prefix scan (one CTA per cloud) ----------
__global__ void __launch_bounds__(1024)
scan_kernel() {
    const int cloud = blockIdx.x;
    const int tid = threadIdx.x;
    const int CPT = NCELLS / 1024;        // 32 cells per thread
    __shared__ int ssum[1024];

    const int base = tid * CPT;
    int s = 0;
    #pragma unroll 8
    for (int c = 0; c < CPT; c++) s += g_cursor[cloud][base + c];
    ssum[tid] = s;
    __syncthreads();
    for (int off = 1; off < 1024; off <<= 1) {
        int v = (tid >= off) ? ssum[tid - off] : 0;
        __syncthreads();
        ssum[tid] += v;
        __syncthreads();
    }
    int run = ssum[tid] - s;              // exclusive prefix for this thread
    for (int c = 0; c < CPT; c++) {
        int cnt = g_cursor[cloud][base + c];
        g_start[cloud][base + c] = run;
        g_cursor[cloud][base + c] = run;  // scatter cursor
        run += cnt;
    }
    if (tid == 1023) g_start[cloud][NCELLS] = run;
}

// ---------- 4. scatter into grid-sorted order ----------
__global__ void scatter_kernel(const float* __restrict__ A,
                               const float* __restrict__ B, int N, int M) {
    int gid = blockIdx.x * blockDim.x + threadIdx.x;
    if (gid >= N + M) return;
    int cloud = (gid >= N);
    int i = cloud ? gid - N : gid;
    const float* src = cloud ? B : A;
    float x = src[3 * i], y = src[3 * i + 1], z = src[3 * i + 2];
    int cell = (cell_coord(z) * G + cell_coord(y)) * G + cell_coord(x);
    int pos = atomicAdd(&g_cursor[cloud][cell], 1);
    g_sorted[cloud][pos] = make_float4(x, y, z, __int_as_float(i));
}

// ---------- 5. warp-cooperative expanding-ring NN query ----------
__global__ void __launch_bounds__(256)
query_kernel(int N, int M) {
    const int wid = (blockIdx.x * blockDim.x + threadIdx.x) >> 5;
    const int lane = threadIdx.x & 31;
    if (wid >= N + M) return;
    const int cq = (wid >= N);            // query cloud
    const int i = cq ? wid - N : wid;
    const int ct = 1 - cq;                // target cloud

    const float4 p = g_sorted[cq][i];     // broadcast load (same addr all lanes)
    const float qx = p.x, qy = p.y, qz = p.z;
    const int cx = cell_coord(qx), cy = cell_coord(qy), cz = cell_coord(qz);
    const int* __restrict__ start = g_start[ct];
    const float4* __restrict__ pts = g_sorted[ct];

    float best = CUDART_INF_F;            // per-lane partial min
    for (int r = 0; r <= G; r++) {
        if (r > 0) {
            // warp-reduce partial mins, then uniform bound check
            float m = best;
            #pragma unroll
            for (int o = 16; o > 0; o >>= 1)
                m = fminf(m, __shfl_xor_sync(0xFFFFFFFFu, m, o));
            // distance from q to nearest face of the scanned cube (radius r-1);
            // faces at/past the grid edge count as +inf (exact with clamping)
            const int rr = r - 1;
            float b = CUDART_INF_F;
            if (cx - rr > 0)     b = fminf(b, qx - (GRID_LO + (cx - rr) * HCELL));
            if (cx + rr < G - 1) b = fminf(b, (GRID_LO + (cx + rr + 1) * HCELL) - qx);
            if (cy - rr > 0)     b = fminf(b, qy - (GRID_LO + (cy - rr) * HCELL));
            if (cy + rr < G - 1) b = fminf(b, (GRID_LO + (cy + rr + 1) * HCELL) - qy);
            if (cz - rr > 0)     b = fminf(b, qz - (GRID_LO + (cz - rr) * HCELL));
            if (cz + rr < G - 1) b = fminf(b, (GRID_LO + (cz + rr + 1) * HCELL) - qz);
            if (m <= b * b) { best = m; break; }   // b==inf when grid exhausted
            best = m;
        }
        // scan Chebyshev ring r (warp-uniform control; lanes stride points)
        const int zlo = max(cz - r, 0), zhi = min(cz + r, G - 1);
        for (int z = zlo; z <= zhi; z++) {
            const bool zf = (z == cz - r) || (z == cz + r);
            const int ylo = max(cy - r, 0), yhi = min(cy + r, G - 1);
            for (int y = ylo; y <= yhi; y++) {
                const bool yf = zf || (y == cy - r) || (y == cy + r);
                const int rowbase = (z * G + y) * G;
                int s, e;
                if (yf) {                 // full x-row: merged contiguous range
                    const int xlo = max(cx - r, 0), xhi = min(cx + r, G - 1);
                    s = start[rowbase + xlo];
                    e = start[rowbase + xhi + 1];
                } else {                  // only the two x-edge cells
                    if (cx - r >= 0) {
                        const int c = rowbase + cx - r;
                        for (int k = start[c] + lane; k < start[c + 1]; k += 32) {
                            float4 t = pts[k];
                            float dx = qx - t.x, dy = qy - t.y, dz = qz - t.z;
                            best = fminf(best, fmaf(dx, dx, fmaf(dy, dy, dz * dz)));
                        }
                    }
                    if (cx + r <= G - 1) {
                        const int c = rowbase + cx + r;
                        s = start[c]; e = start[c + 1];
                        for (int k = s + lane; k < e; k += 32) {
                            float4 t = pts[k];
                            float dx = qx - t.x, dy = qy - t.y, dz = qz - t.z;
                            best = fminf(best, fmaf(dx, dx, fmaf(dy, dy, dz * dz)));
                        }
                    }
                    continue;
                }
                for (int k = s + lane; k < e; k += 32) {   // coalesced float4
                    float4 t = pts[k];
                    float dx = qx - t.x, dy = qy - t.y, dz = qz - t.z;
                    best = fminf(best, fmaf(dx, dx, fmaf(dy, dy, dz * dz)));
                }
            }
        }
    }

    if (lane == 0) {
        const int orig = __float_as_int(p.w);
        g_dist[(cq ? N : 0) + orig] = sqrtf(best);
    }
}

// ---------- 6-7. deterministic two-stage sum ----------
__global__ void __launch_bounds__(RED_THREADS)
reduce1_kernel(int total) {
    __shared__ float ssum[RED_THREADS / 32];
    const int per = (total + RED_CTAS - 1) / RED_CTAS;
    const int base = blockIdx.x * per;
    const int end = min(base + per, total);

    float acc = 0.0f;
    for (int i = base + threadIdx.x; i < end; i += RED_THREADS)
        acc += g_dist[i];
    #pragma unroll
    for (int o = 16; o > 0; o >>= 1)
        acc += __shfl_down_sync(0xFFFFFFFFu, acc, o);
    if ((threadIdx.x & 31) == 0) ssum[threadIdx.x >> 5] = acc;
    __syncthreads();
    if (threadIdx.x == 0) {
        float v = 0.0f;
        #pragma unroll
        for (int w = 0; w < RED_THREADS / 32; w++) v += ssum[w];
        g_part[blockIdx.x] = v;
    }
}

__global__ void reduce2_kernel(float* __restrict__ out) {
    float acc = 0.0f;
    #pragma unroll
    for (int k = 0; k < RED_CTAS / 32; k++)
        acc += g_part[threadIdx.x + 32 * k];
    #pragma unroll
    for (int o = 16; o > 0; o >>= 1)
        acc += __shfl_down_sync(0xFFFFFFFFu, acc, o);
    if (threadIdx.x == 0) out[0] = acc * 0.001f;
}

extern "C" void kernel_launch(void* const* d_in, const int* in_sizes, int n_in,
                              void* d_out, int out_size)
{
    const float* A = (const float*)d_in[0];   // target_pc [N,3]
    const float* B = (const float*)d_in[1];   // output_pc [M,3]
    const int N = in_sizes[0] / 3;
    const int M = in_sizes[1] / 3;
    const int total = N + M;

    zero_kernel<<<(2 * NCELLS + 1023) / 1024, 1024>>>();
    build_kernel<<<(total + 255) / 256, 256>>>(A, B, N, M);
    scan_kernel<<<2, 1024>>>();
    scatter_kernel<<<(total + 255) / 256, 256>>>(A, B, N, M);
    query_kernel<<<(total * 32 + 255) / 256, 256>>>(N, M);   // one warp / query
    reduce1_kernel<<<RED_CTAS, RED_THREADS>>>(total);
    reduce2_kernel<<<1, 32>>>((float*)d_out);
}

// round 9
// speedup vs baseline: 5.1776x; 1.0897x over previous
#include <cuda_runtime.h>
#include <math_constants.h>

// ============================================================
// ChamferLoss via exact grid NN, fixed-footprint two-phase search.
// Phase 1: warp per query scans fixed 3x3x3 cell block (9 merged x-rows).
//   Every interior face of the block is >= h away; edge faces are exact
//   because clamped outliers live in edge cells (inside the block).
//   If best <= bound^2 -> exact, write. Else append to fallback list.
// Phase 2: failed queries brute-force the whole target cloud (warp-coop,
//   coalesced float4). Result order-invariant (pure min) => deterministic.
// Pipeline: zero -> hist -> scan -> scatter -> phase1 -> fallback -> reduce.
// ============================================================

#define G 32
#define NCELLS (G * G * G)
#define GRID_LO (-6.0f)
#define HCELL 0.375f             // 12/32
#define INV_H (32.0f / 12.0f)
#define MAXPTS 16384
#define RED_CTAS 64
#define RED_THREADS 256
#define FB_WARPS 4096            // fallback kernel total warps (static grid)

__device__ float4 g_sorted[2][MAXPTS];
__device__ int    g_start[2][NCELLS + 1];
__device__ int    g_cursor[2][NCELLS];
__device__ float  g_dist[2 * MAXPTS];
__device__ float  g_part[RED_CTAS];
__device__ int    g_fail[2 * MAXPTS];
__device__ int    g_fail_cnt;

__device__ __forceinline__ int cell_coord(float v) {
    int c = (int)((v - GRID_LO) * INV_H);
    return min(max(c, 0), G - 1);
}

// ---------- 1. zero cursors + fail counter ----------
__global__ void zero_kernel() {
    int i = blockIdx.x * 1024 + threadIdx.x;
    if (i < 2 * NCELLS) ((int*)g_cursor)[i] = 0;
    if (i == 0) g_fail_cnt = 0;
}

// ---------- 2. histogram ----------
__global__ void build_kernel(const float* __restrict__ A,
                             const float* __restrict__ B, int N, int M) {
    int gid = blockIdx.x * blockDim.x + threadIdx.x;
    if (gid >= N + M) return;
    int cloud = (gid >= N);
    int i = cloud ? gid - N : gid;
    const float* src = cloud ? B : A;
    float x = src[3 * i], y = src[3 * i + 1], z = src[3 * i + 2];
    int cell = (cell_coord(z) * G + cell_coord(y)) * G + cell_coord(x);
    atomicAdd(&g_cursor[cloud][cell], 1);
}

// ---------- 3. exclusive prefix scan (one CTA per cloud) ----------
__global__ void __launch_bounds__(1024)
scan_kernel() {
    const int cloud = blockIdx.x;
    const int tid = threadIdx.x;
    const int CPT = NCELLS / 1024;        // 32 cells per thread
    __shared__ int ssum[1024];

    const int base = tid * CPT;
    int s = 0;
    #pragma unroll 8
    for (int c = 0; c < CPT; c++) s += g_cursor[cloud][base + c];
    ssum[tid] = s;
    __syncthreads();
    for (int off = 1; off < 1024; off <<= 1) {
        int v = (tid >= off) ? ssum[tid - off] : 0;
        __syncthreads();
        ssum[tid] += v;
        __syncthreads();
    }
    int run = ssum[tid] - s;
    for (int c = 0; c < CPT; c++) {
        int cnt = g_cursor[cloud][base + c];
        g_start[cloud][base + c] = run;
        g_cursor[cloud][base + c] = run;  // scatter cursor
        run += cnt;
    }
    if (tid == 1023) g_start[cloud][NCELLS] = run;
}

// ---------- 4. scatter into grid-sorted order ----------
__global__ void scatter_kernel(const float* __restrict__ A,
                               const float* __restrict__ B, int N, int M) {
    int gid = blockIdx.x * blockDim.x + threadIdx.x;
    if (gid >= N + M) return;
    int cloud = (gid >= N);
    int i = cloud ? gid - N : gid;
    const float* src = cloud ? B : A;
    float x = src[3 * i], y = src[3 * i + 1], z = src[3 * i + 2];
    int cell = (cell_coord(z) * G + cell_coord(y)) * G + cell_coord(x);
    int pos = atomicAdd(&g_cursor[cloud][cell], 1);
    g_sorted[cloud][pos] = make_float4(x, y, z, __int_as_float(i));
}

// ---------- 5. phase 1: fixed 3x3x3 warp-cooperative scan ----------
__global__ void __launch_bounds__(256)
query_kernel(int N, int M) {
    const int wid = (blockIdx.x * blockDim.x + threadIdx.x) >> 5;
    const int lane = threadIdx.x & 31;
    if (wid >= N + M) return;
    const int cq = (wid >= N);
    const int i = cq ? wid - N : wid;
    const int ct = 1 - cq;
    const int nq_off = cq ? N : 0;

    const float4 p = g_sorted[cq][i];
    const float qx = p.x, qy = p.y, qz = p.z;
    const int cx = cell_coord(qx), cy = cell_coord(qy), cz = cell_coord(qz);
    const int* __restrict__ start = g_start[ct];
    const float4* __restrict__ pts = g_sorted[ct];

    const int xlo = max(cx - 1, 0), xhi = min(cx + 1, G - 1);
    const int ylo = max(cy - 1, 0), yhi = min(cy + 1, G - 1);
    const int zlo = max(cz - 1, 0), zhi = min(cz + 1, G - 1);

    float best = CUDART_INF_F;
    for (int z = zlo; z <= zhi; z++) {
        for (int y = ylo; y <= yhi; y++) {
            const int rowbase = (z * G + y) * G;
            const int s = start[rowbase + xlo];
            const int e = start[rowbase + xhi + 1];
            for (int k = s + lane; k < e; k += 32) {   // coalesced float4
                float4 t = pts[k];
                float dx = qx - t.x, dy = qy - t.y, dz = qz - t.z;
                best = fminf(best, fmaf(dx, dx, fmaf(dy, dy, dz * dz)));
            }
        }
    }
    #pragma unroll
    for (int o = 16; o > 0; o >>= 1)
        best = fminf(best, __shfl_xor_sync(0xFFFFFFFFu, best, o));

    // bound = distance to nearest interior face of the 3^3 block.
    // Faces at/past the grid edge => +inf: clamped outliers live in edge
    // cells, which ARE inside the block in that direction, so nothing
    // unscanned lies beyond such a face.
    float b = CUDART_INF_F;
    if (cx - 1 > 0)     b = fminf(b, qx - (GRID_LO + (cx - 1) * HCELL));
    if (cx + 1 < G - 1) b = fminf(b, (GRID_LO + (cx + 2) * HCELL) - qx);
    if (cy - 1 > 0)     b = fminf(b, qy - (GRID_LO + (cy - 1) * HCELL));
    if (cy + 1 < G - 1) b = fminf(b, (GRID_LO + (cy + 2) * HCELL) - qy);
    if (cz - 1 > 0)     b = fminf(b, qz - (GRID_LO + (cz - 1) * HCELL));
    if (cz + 1 < G - 1) b = fminf(b, (GRID_LO + (cz + 2) * HCELL) - qz);

    if (lane == 0) {
        if (best <= b * b) {
            g_dist[nq_off + __float_as_int(p.w)] = sqrtf(best);
        } else {
            int slot = atomicAdd(&g_fail_cnt, 1);
            g_fail[slot] = wid;           // sorted-global query id
        }
    }
}

// ---------- 6. phase 2: brute-force fallback for failed queries ----------
__global__ void __launch_bounds__(256)
fallback_kernel(int N, int M) {
    const int warp_gid = (blockIdx.x * blockDim.x + threadIdx.x) >> 5;
    const int lane = threadIdx.x & 31;
    const int cnt = g_fail_cnt;

    for (int f = warp_gid; f < cnt; f += FB_WARPS) {
        const int wid = g_fail[f];
        const int cq = (wid >= N);
        const int i = cq ? wid - N : wid;
        const int ct = 1 - cq;
        const int nt = cq ? N : M;        // target count (ct cloud)
        const float4 p = g_sorted[cq][i];
        const float qx = p.x, qy = p.y, qz = p.z;
        const float4* __restrict__ pts = g_sorted[ct];

        float best = CUDART_INF_F;
        for (int k = lane; k < nt; k += 32) {
            float4 t = pts[k];
            float dx = qx - t.x, dy = qy - t.y, dz = qz - t.z;
            best = fminf(best, fmaf(dx, dx, fmaf(dy, dy, dz * dz)));
        }
        #pragma unroll
        for (int o = 16; o > 0; o >>= 1)
            best = fminf(best, __shfl_xor_sync(0xFFFFFFFFu, best, o));
        if (lane == 0)
            g_dist[(cq ? N : 0) + __float_as_int(p.w)] = sqrtf(best);
    }
}

// ---------- 7-8. deterministic two-stage sum ----------
__global__ void __launch_bounds__(RED_THREADS)
reduce1_kernel(int total) {
    __shared__ float ssum[RED_THREADS / 32];
    const int per = (total + RED_CTAS - 1) / RED_CTAS;
    const int base = blockIdx.x * per;
    const int end = min(base + per, total);

    float acc = 0.0f;
    for (int i = base + threadIdx.x; i < end; i += RED_THREADS)
        acc += g_dist[i];
    #pragma unroll
    for (int o = 16; o > 0; o >>= 1)
        acc += __shfl_down_sync(0xFFFFFFFFu, acc, o);
    if ((threadIdx.x & 31) == 0) ssum[threadIdx.x >> 5] = acc;
    __syncthreads();
    if (threadIdx.x == 0) {
        float v = 0.0f;
        #pragma unroll
        for (int w = 0; w < RED_THREADS / 32; w++) v += ssum[w];
        g_part[blockIdx.x] = v;
    }
}

__global__ void reduce2_kernel(float* __restrict__ out) {
    float acc = 0.0f;
    #pragma unroll
    for (int k = 0; k < RED_CTAS / 32; k++)
        acc += g_part[threadIdx.x + 32 * k];
    #pragma unroll
    for (int o = 16; o > 0; o >>= 1)
        acc += __shfl_down_sync(0xFFFFFFFFu, acc, o);
    if (threadIdx.x == 0) out[0] = acc * 0.001f;
}

extern "C" void kernel_launch(void* const* d_in, const int* in_sizes, int n_in,
                              void* d_out, int out_size)
{
    const float* A = (const float*)d_in[0];   // target_pc [N,3]
    const float* B = (const float*)d_in[1];   // output_pc [M,3]
    const int N = in_sizes[0] / 3;
    const int M = in_sizes[1] / 3;
    const int total = N + M;

    zero_kernel<<<(2 * NCELLS + 1023) / 1024, 1024>>>();
    build_kernel<<<(total + 255) / 256, 256>>>(A, B, N, M);
    scan_kernel<<<2, 1024>>>();
    scatter_kernel<<<(total + 255) / 256, 256>>>(A, B, N, M);
    query_kernel<<<(total * 32 + 255) / 256, 256>>>(N, M);     // warp/query
    fallback_kernel<<<FB_WARPS / 8, 256>>>(N, M);              // static grid
    reduce1_kernel<<<RED_CTAS, RED_THREADS>>>(total);
    reduce2_kernel<<<1, 32>>>((float*)d_out);
}

// round 10
// speedup vs baseline: 11.4786x; 2.2170x over previous
#include <cuda_runtime.h>
#include <math_constants.h>

// ============================================================
// ChamferLoss brute force, tuned occupancy.
// s = q.b - 0.5|b|^2 via fma.rn.f32x2 (2 queries/op); min d^2 = qn - 2*max_j s.
// QPT=8 (56-61 regs) + grid 8x37x2 = 592 CTAs = 4/SM -> 8 warps/SMSP to
// cover the latency stalls seen at issue=48% in round 6.
// Cross-CTA min: atomicMax on ~bits(dsq) (identity 0 -> no init kernel);
// 2-stage parallel reduce resets state to 0 for the next graph replay.
// ============================================================

#define THREADS 256
#define QPT 8            // queries per thread (4 packed pairs)
#define QPAIRS (QPT / 2)
#define QBLOCKS 8        // 8 * 256 * 8 = 16384
#define TCHUNK 443       // 37 chunks cover 16384 (37*443 = 16391)
#define NCHUNKS 37
#define MAXPTS 16384
#define RED_CTAS 64
#define RED_THREADS 256

__device__ unsigned g_min[2 * MAXPTS];   // zero-init BSS; holds ~bits(min dsq)
__device__ float g_part[RED_CTAS];

__device__ __forceinline__ unsigned long long pack2(float lo, float hi) {
    unsigned long long r;
    asm("mov.b64 %0, {%1, %2};" : "=l"(r) : "f"(lo), "f"(hi));
    return r;
}
__device__ __forceinline__ void unpack2(unsigned long long v, float& lo, float& hi) {
    asm("mov.b64 {%0, %1}, %2;" : "=f"(lo), "=f"(hi) : "l"(v));
}
__device__ __forceinline__ unsigned long long fma2(unsigned long long a,
                                                   unsigned long long b,
                                                   unsigned long long c) {
    unsigned long long d;
    asm("fma.rn.f32x2 %0, %1, %2, %3;" : "=l"(d) : "l"(a), "l"(b), "l"(c));
    return d;
}

__global__ void __launch_bounds__(THREADS, 4)
chamfer_min_kernel(const float* __restrict__ A, const float* __restrict__ B,
                   int N, int M)
{
    const int tid = threadIdx.x;
    const int dir = blockIdx.z;
    const float* __restrict__ P = dir ? B : A;   // queries
    const float* __restrict__ T = dir ? A : B;   // targets
    const int nq = dir ? M : N;
    const int nt = dir ? N : M;
    unsigned* minarr = g_min + dir * MAXPTS;

    // per target: {bx,bx},{by,by} | {bz,bz},{nhb,nhb}; +1 pad entry for prefetch
    __shared__ ulonglong2 sv[(TCHUNK + 1) * 2];  // ~14.2 KB

    const int tbase = blockIdx.y * TCHUNK;
    if (tbase >= nt) return;
    const int nload = min(TCHUNK, nt - tbase);

    for (int j = tid; j < nload; j += THREADS) {
        float bx = T[(tbase + j) * 3 + 0];
        float by = T[(tbase + j) * 3 + 1];
        float bz = T[(tbase + j) * 3 + 2];
        float nhb = -0.5f * fmaf(bx, bx, fmaf(by, by, bz * bz));
        sv[2 * j]     = make_ulonglong2(pack2(bx, bx), pack2(by, by));
        sv[2 * j + 1] = make_ulonglong2(pack2(bz, bz), pack2(nhb, nhb));
    }
    if (tid == 0) {   // pad so prefetch of j+1 is always in-bounds
        sv[2 * nload]     = make_ulonglong2(0ull, 0ull);
        sv[2 * nload + 1] = make_ulonglong2(0ull, 0ull);
    }
    __syncthreads();

    // register-resident queries, packed in pairs
    const int qbase = blockIdx.x * (THREADS * QPT) + tid;
    float qfx[QPT], qfy[QPT], qfz[QPT], qn[QPT], ms[QPT];
    #pragma unroll
    for (int q = 0; q < QPT; q++) {
        int qi = qbase + q * THREADS;
        int base = (qi < nq ? qi : 0) * 3;
        qfx[q] = P[base + 0];
        qfy[q] = P[base + 1];
        qfz[q] = P[base + 2];
        qn[q] = fmaf(qfx[q], qfx[q], fmaf(qfy[q], qfy[q], qfz[q] * qfz[q]));
        ms[q] = -CUDART_INF_F;
    }
    unsigned long long qx[QPAIRS], qy[QPAIRS], qz[QPAIRS];
    #pragma unroll
    for (int p = 0; p < QPAIRS; p++) {
        qx[p] = pack2(qfx[2 * p], qfx[2 * p + 1]);
        qy[p] = pack2(qfy[2 * p], qfy[2 * p + 1]);
        qz[p] = pack2(qfz[2 * p], qfz[2 * p + 1]);
    }

    // main loop: register double-buffer hides LDS latency behind one
    // full iteration of math (12 FFMA2 + 8 FMNMX per target).
    ulonglong2 c0 = sv[0], c1 = sv[1];
    #pragma unroll 2
    for (int j = 0; j < nload; j++) {
        const ulonglong2 n0 = sv[2 * (j + 1)];       // prefetch next target
        const ulonglong2 n1 = sv[2 * (j + 1) + 1];
        #pragma unroll
        for (int p = 0; p < QPAIRS; p++) {
            unsigned long long t = fma2(qz[p], c1.x, c1.y);  // qz*bz - .5|b|^2
            t = fma2(qy[p], c0.y, t);
            t = fma2(qx[p], c0.x, t);                        // s
            float s0, s1;
            unpack2(t, s0, s1);
            ms[2 * p]     = fmaxf(ms[2 * p],     s0);
            ms[2 * p + 1] = fmaxf(ms[2 * p + 1], s1);
        }
        c0 = n0; c1 = n1;
    }

    // dsq = max(qn - 2*max_s, 0); cross-CTA min == atomicMax of ~bits (dsq >= 0)
    #pragma unroll
    for (int q = 0; q < QPT; q++) {
        int qi = qbase + q * THREADS;
        if (qi < nq) {
            float dsq = fmaxf(fmaf(-2.0f, ms[q], qn[q]), 0.0f);
            atomicMax(&minarr[qi], ~(unsigned)__float_as_int(dsq));
        }
    }
}

// Stage 1: 64 CTAs, each sums sqrt over a fixed slice and resets g_min
// to 0 for the next graph replay. Deterministic partition.
__global__ void __launch_bounds__(RED_THREADS)
reduce1_kernel(int total) {
    __shared__ float ssum[RED_THREADS / 32];
    const int per = (total + RED_CTAS - 1) / RED_CTAS;
    const int base = blockIdx.x * per;
    const int end = min(base + per, total);

    float acc = 0.0f;
    for (int i = base + threadIdx.x; i < end; i += RED_THREADS) {
        unsigned u = g_min[i];
        acc += sqrtf(__int_as_float((int)~u));
        g_min[i] = 0u;
    }
    #pragma unroll
    for (int o = 16; o > 0; o >>= 1)
        acc += __shfl_down_sync(0xFFFFFFFFu, acc, o);
    if ((threadIdx.x & 31) == 0) ssum[threadIdx.x >> 5] = acc;
    __syncthreads();
    if (threadIdx.x == 0) {
        float v = 0.0f;
        #pragma unroll
        for (int w = 0; w < RED_THREADS / 32; w++) v += ssum[w];
        g_part[blockIdx.x] = v;
    }
}

// Stage 2: one warp folds the 64 partials.
__global__ void reduce2_kernel(float* __restrict__ out) {
    float acc = 0.0f;
    #pragma unroll
    for (int k = 0; k < RED_CTAS / 32; k++)
        acc += g_part[threadIdx.x + 32 * k];
    #pragma unroll
    for (int o = 16; o > 0; o >>= 1)
        acc += __shfl_down_sync(0xFFFFFFFFu, acc, o);
    if (threadIdx.x == 0) out[0] = acc * 0.001f;
}

extern "C" void kernel_launch(void* const* d_in, const int* in_sizes, int n_in,
                              void* d_out, int out_size)
{
    const float* A = (const float*)d_in[0];   // target_pc [N,3]
    const float* B = (const float*)d_in[1];   // output_pc [M,3]
    const int N = in_sizes[0] / 3;
    const int M = in_sizes[1] / 3;

    dim3 grid(QBLOCKS, NCHUNKS, 2);           // 8*37*2 = 592 CTAs = 4/SM
    chamfer_min_kernel<<<grid, THREADS>>>(A, B, N, M);

    reduce1_kernel<<<RED_CTAS, RED_THREADS>>>(N + M);
    reduce2_kernel<<<1, 32>>>((float*)d_out);
}

// round 11
// speedup vs baseline: 12.1483x; 1.0583x over previous
#include <cuda_runtime.h>
#include <math_constants.h>

// ============================================================
// ChamferLoss: x-sorted slab pruning on top of the proven packed-FFMA2
// brute-force kernel.
//  - bucket-sort both clouds by x (256 bins)
//  - main kernel: champion inner loop (fma.rn.f32x2, dot-expansion,
//    SMEM-duplicated targets), but each warp owns 256 CONTIGUOUS sorted
//    queries and skips chunks outside [wmin-R, wmax+R] (warp-uniform).
//    Exactness: any query ending with dsq <= R^2 has its true NN scanned.
//  - fallback kernel: queries with dsq > R^2 rescan the sorted window
//    |tx - qx| <= sqrt(dsq)  (exact, tiny).
//  - deterministic: per-query value is the true min; sum in orig order.
// ============================================================

#define THREADS 256
#define QPT 8
#define QPAIRS (QPT / 2)
#define QBLOCKS 8              // 8 CTAs x 8 warps x 256 q = 16384
#define TCHUNK 128
#define NCHUNKS 128            // 128 x 128 = 16384
#define BINS 256
#define GRID_LO (-6.0f)
#define BINW 0.046875f         // 12/256
#define INV_BINW (256.0f / 12.0f)
#define MAXPTS 16384
#define RADIUS 0.22f
#define R2 (RADIUS * RADIUS)
#define RED_CTAS 64
#define RED_THREADS 256

__device__ float4   g_sorted[2][MAXPTS];
__device__ int      g_bincnt[2][BINS];
__device__ int      g_binstart[2][BINS + 1];
__device__ int      g_curs[2][BINS];
__device__ float    g_chunklo[2][NCHUNKS];
__device__ float    g_chunkhi[2][NCHUNKS];
__device__ unsigned g_min[2 * MAXPTS];   // ~bits(min dsq); identity 0
__device__ float    g_part[RED_CTAS];

__device__ __forceinline__ unsigned long long pack2(float lo, float hi) {
    unsigned long long r;
    asm("mov.b64 %0, {%1, %2};" : "=l"(r) : "f"(lo), "f"(hi));
    return r;
}
__device__ __forceinline__ void unpack2(unsigned long long v, float& lo, float& hi) {
    asm("mov.b64 {%0, %1}, %2;" : "=f"(lo), "=f"(hi) : "l"(v));
}
__device__ __forceinline__ unsigned long long fma2(unsigned long long a,
                                                   unsigned long long b,
                                                   unsigned long long c) {
    unsigned long long d;
    asm("fma.rn.f32x2 %0, %1, %2, %3;" : "=l"(d) : "l"(a), "l"(b), "l"(c));
    return d;
}
__device__ __forceinline__ int xbin(float x) {
    int b = (int)((x - GRID_LO) * INV_BINW);
    return min(max(b, 0), BINS - 1);
}

// ---------- 1. zero bin counts ----------
__global__ void zero_kernel() {
    ((int*)g_bincnt)[threadIdx.x] = 0;   // 512 threads
}

// ---------- 2. histogram by x ----------
__global__ void hist_kernel(const float* __restrict__ A,
                            const float* __restrict__ B, int N, int M) {
    int gid = blockIdx.x * blockDim.x + threadIdx.x;
    if (gid >= N + M) return;
    int cl = (gid >= N);
    int i = cl ? gid - N : gid;
    const float* src = cl ? B : A;
    atomicAdd(&g_bincnt[cl][xbin(src[3 * i])], 1);
}

// ---------- 3. scan + chunk x-bounds ----------
__global__ void __launch_bounds__(512)
scan_kernel(int N, int M) {
    __shared__ int s[512];
    const int tid = threadIdx.x;
    const int cl = tid >> 8, b = tid & 255;
    const int cnt = g_bincnt[cl][b];
    s[tid] = cnt;
    __syncthreads();
    #pragma unroll
    for (int off = 1; off < 256; off <<= 1) {
        int v = (b >= off) ? s[tid - off] : 0;
        __syncthreads();
        s[tid] += v;
        __syncthreads();
    }
    const int incl = s[tid];
    g_binstart[cl][b] = incl - cnt;
    g_curs[cl][b] = incl - cnt;
    if (b == 255) g_binstart[cl][256] = incl;
    __syncthreads();

    if (tid < 2 * NCHUNKS) {
        const int cc = tid >> 7;                   // cloud
        const int c = tid & (NCHUNKS - 1);         // chunk
        const int nt = cc ? M : N;
        const int lo_pos = c * TCHUNK;
        if (lo_pos >= nt) {
            g_chunklo[cc][c] = 1e9f; g_chunkhi[cc][c] = -1e9f;
        } else {
            const int hi_pos = min((c + 1) * TCHUNK, nt) - 1;
            int bl, bh;
            {   // smallest bin with inclusive > pos
                int lo = 0, hi = 255;
                while (lo < hi) { int m = (lo + hi) >> 1;
                    if (s[cc * 256 + m] > lo_pos) hi = m; else lo = m + 1; }
                bl = lo;
                lo = 0; hi = 255;
                while (lo < hi) { int m = (lo + hi) >> 1;
                    if (s[cc * 256 + m] > hi_pos) hi = m; else lo = m + 1; }
                bh = lo;
            }
            // conservative: pad by one bin width for fp-edge safety
            g_chunklo[cc][c] = GRID_LO + bl * BINW - BINW;
            g_chunkhi[cc][c] = GRID_LO + (bh + 1) * BINW + BINW;
        }
    }
}

// ---------- 4. scatter (x-bucket sorted, orig index in .w) ----------
__global__ void scatter_kernel(const float* __restrict__ A,
                               const float* __restrict__ B, int N, int M) {
    int gid = blockIdx.x * blockDim.x + threadIdx.x;
    if (gid >= N + M) return;
    int cl = (gid >= N);
    int i = cl ? gid - N : gid;
    const float* src = cl ? B : A;
    float x = src[3 * i], y = src[3 * i + 1], z = src[3 * i + 2];
    int pos = atomicAdd(&g_curs[cl][xbin(x)], 1);
    g_sorted[cl][pos] = make_float4(x, y, z, __int_as_float(i));
}

// ---------- 5. main: champion loop + warp-window chunk skip ----------
__global__ void __launch_bounds__(THREADS, 4)
chamfer_min_kernel(int N, int M)
{
    const int tid = threadIdx.x;
    const int lane = tid & 31;
    const int dir = blockIdx.z;
    const int cq = dir;                    // query cloud (dir0: A)
    const int ct = 1 - dir;
    const int nq = dir ? M : N;
    const int nt = dir ? N : M;
    const float4* __restrict__ Q = g_sorted[cq];
    unsigned* minarr = g_min + dir * MAXPTS;

    __shared__ ulonglong2 sv[(TCHUNK + 1) * 2];

    const int chunk = blockIdx.y;
    const int tbase = chunk * TCHUNK;
    if (tbase >= nt) return;
    const int nload = min(TCHUNK, nt - tbase);

    // warp-contiguous queries
    const int qbase_w = (blockIdx.x * (THREADS / 32) + (tid >> 5)) * 256;
    float qfx[QPT], qfy[QPT], qfz[QPT], qn[QPT], ms[QPT];
    float wmin = CUDART_INF_F, wmax = -CUDART_INF_F;
    #pragma unroll
    for (int q = 0; q < QPT; q++) {
        int qi = qbase_w + q * 32 + lane;
        bool v = (qi < nq);
        float4 s = Q[v ? qi : 0];
        qfx[q] = s.x; qfy[q] = s.y; qfz[q] = s.z;
        qn[q] = fmaf(s.x, s.x, fmaf(s.y, s.y, s.z * s.z));
        ms[q] = -CUDART_INF_F;
        if (v) { wmin = fminf(wmin, s.x); wmax = fmaxf(wmax, s.x); }
    }
    #pragma unroll
    for (int o = 16; o > 0; o >>= 1) {
        wmin = fminf(wmin, __shfl_xor_sync(0xFFFFFFFFu, wmin, o));
        wmax = fmaxf(wmax, __shfl_xor_sync(0xFFFFFFFFu, wmax, o));
    }
    const float clo = g_chunklo[ct][chunk];
    const float chi = g_chunkhi[ct][chunk];
    const bool wskip = (clo > wmax + RADIUS) || (chi < wmin - RADIUS);

    if (__syncthreads_and(wskip)) return;   // whole CTA irrelevant

    // tile load (duplicated packed layout)
    for (int j = tid; j < nload; j += THREADS) {
        float4 t = g_sorted[ct][tbase + j];
        float nhb = -0.5f * fmaf(t.x, t.x, fmaf(t.y, t.y, t.z * t.z));
        sv[2 * j]     = make_ulonglong2(pack2(t.x, t.x), pack2(t.y, t.y));
        sv[2 * j + 1] = make_ulonglong2(pack2(t.z, t.z), pack2(nhb, nhb));
    }
    if (tid == 0) {
        sv[2 * nload]     = make_ulonglong2(0ull, 0ull);
        sv[2 * nload + 1] = make_ulonglong2(0ull, 0ull);
    }
    __syncthreads();

    if (wskip) return;

    unsigned long long qx[QPAIRS], qy[QPAIRS], qz[QPAIRS];
    #pragma unroll
    for (int p = 0; p < QPAIRS; p++) {
        qx[p] = pack2(qfx[2 * p], qfx[2 * p + 1]);
        qy[p] = pack2(qfy[2 * p], qfy[2 * p + 1]);
        qz[p] = pack2(qfz[2 * p], qfz[2 * p + 1]);
    }

    ulonglong2 c0 = sv[0], c1 = sv[1];
    #pragma unroll 2
    for (int j = 0; j < nload; j++) {
        const ulonglong2 n0 = sv[2 * (j + 1)];
        const ulonglong2 n1 = sv[2 * (j + 1) + 1];
        #pragma unroll
        for (int p = 0; p < QPAIRS; p++) {
            unsigned long long t = fma2(qz[p], c1.x, c1.y);
            t = fma2(qy[p], c0.y, t);
            t = fma2(qx[p], c0.x, t);
            float s0, s1;
            unpack2(t, s0, s1);
            ms[2 * p]     = fmaxf(ms[2 * p],     s0);
            ms[2 * p + 1] = fmaxf(ms[2 * p + 1], s1);
        }
        c0 = n0; c1 = n1;
    }

    #pragma unroll
    for (int q = 0; q < QPT; q++) {
        int qi = qbase_w + q * 32 + lane;
        if (qi < nq) {
            float dsq = fmaxf(fmaf(-2.0f, ms[q], qn[q]), 0.0f);
            int orig = __float_as_int(__ldg(((const float*)(Q + qi)) + 3));
            atomicMax(&minarr[orig], ~(unsigned)__float_as_int(dsq));
        }
    }
}

// ---------- 6. fallback: exact window rescan for dsq > R^2 ----------
__global__ void __launch_bounds__(256)
fallback_kernel(int N, int M)
{
    const int gw = (blockIdx.x * blockDim.x + threadIdx.x) >> 5;
    const int lane = threadIdx.x & 31;
    if (gw >= N + M) return;
    const int cl = (gw >= N);
    const int i = cl ? gw - N : gw;
    const int ct = 1 - cl;
    const int nt = cl ? N : M;

    const float4 p = g_sorted[cl][i];
    const int slot = (cl ? MAXPTS : 0) + __float_as_int(p.w);
    const unsigned u = g_min[slot];
    const unsigned TMIN = ~__float_as_uint(R2);
    if (u >= TMIN) return;                 // dsq <= R^2: already exact

    int s, e;
    if (u == 0u) { s = 0; e = nt; }        // never scanned: full range
    else {
        float d = sqrtf(__int_as_float((int)~u));
        int bl = max((int)((p.x - d - GRID_LO) * INV_BINW) - 1, 0);
        int bh = min((int)((p.x + d - GRID_LO) * INV_BINW) + 1, BINS - 1);
        s = g_binstart[ct][bl];
        e = g_binstart[ct][bh + 1];
    }
    float best = CUDART_INF_F;
    for (int k = s + lane; k < e; k += 32) {
        float4 t = g_sorted[ct][k];
        float dx = p.x - t.x, dy = p.y - t.y, dz = p.z - t.z;
        best = fminf(best, fmaf(dx, dx, fmaf(dy, dy, dz * dz)));
    }
    #pragma unroll
    for (int o = 16; o > 0; o >>= 1)
        best = fminf(best, __shfl_xor_sync(0xFFFFFFFFu, best, o));
    if (lane == 0)
        g_min[slot] = ~(unsigned)__float_as_int(best);  // exact true min
}

// ---------- 7-8. deterministic two-stage sum (+state reset) ----------
__global__ void __launch_bounds__(RED_THREADS)
reduce1_kernel(int total) {
    __shared__ float ssum[RED_THREADS / 32];
    const int per = (total + RED_CTAS - 1) / RED_CTAS;
    const int base = blockIdx.x * per;
    const int end = min(base + per, total);

    float acc = 0.0f;
    for (int i = base + threadIdx.x; i < end; i += RED_THREADS) {
        unsigned u = g_min[i];
        acc += sqrtf(__int_as_float((int)~u));
        g_min[i] = 0u;
    }
    #pragma unroll
    for (int o = 16; o > 0; o >>= 1)
        acc += __shfl_down_sync(0xFFFFFFFFu, acc, o);
    if ((threadIdx.x & 31) == 0) ssum[threadIdx.x >> 5] = acc;
    __syncthreads();
    if (threadIdx.x == 0) {
        float v = 0.0f;
        #pragma unroll
        for (int w = 0; w < RED_THREADS / 32; w++) v += ssum[w];
        g_part[blockIdx.x] = v;
    }
}

__global__ void reduce2_kernel(float* __restrict__ out) {
    float acc = 0.0f;
    #pragma unroll
    for (int k = 0; k < RED_CTAS / 32; k++)
        acc += g_part[threadIdx.x + 32 * k];
    #pragma unroll
    for (int o = 16; o > 0; o >>= 1)
        acc += __shfl_down_sync(0xFFFFFFFFu, acc, o);
    if (threadIdx.x == 0) out[0] = acc * 0.001f;
}

extern "C" void kernel_launch(void* const* d_in, const int* in_sizes, int n_in,
                              void* d_out, int out_size)
{
    const float* A = (const float*)d_in[0];   // target_pc [N,3]
    const float* B = (const float*)d_in[1];   // output_pc [M,3]
    const int N = in_sizes[0] / 3;
    const int M = in_sizes[1] / 3;
    const int total = N + M;

    zero_kernel<<<1, 512>>>();
    hist_kernel<<<(total + 255) / 256, 256>>>(A, B, N, M);
    scan_kernel<<<1, 512>>>(N, M);
    scatter_kernel<<<(total + 255) / 256, 256>>>(A, B, N, M);

    dim3 grid(QBLOCKS, NCHUNKS, 2);           // 8 x 128 x 2 = 2048 CTAs
    chamfer_min_kernel<<<grid, THREADS>>>(N, M);

    fallback_kernel<<<(total * 32 + 255) / 256, 256>>>(N, M);
    reduce1_kernel<<<RED_CTAS, RED_THREADS>>>(total);
    reduce2_kernel<<<1, 32>>>((float*)d_out);
}

// round 12
// speedup vs baseline: 13.9017x; 1.1443x over previous
#include <cuda_runtime.h>
#include <math_constants.h>

// ============================================================
// ChamferLoss via exact 1-D sorted-window NN.
//  - bucket-sort both clouds by x (256 bins)  [4 small kernels]
//  - query kernel, ONE WARP PER QUERY:
//      seed: expand bins around query until non-empty, scan -> d0 (upper bd)
//      window: scan all targets with |tx-qx| <= d0 (+1 bin pad) -> exact NN
//    Loop bounds warp-uniform; loads lane-strided coalesced float4.
//    Single writer per query into g_dist[orig] -> bit-deterministic.
//  - two-stage deterministic sum.
// ============================================================

#define BINS 256
#define GRID_LO (-6.0f)
#define INV_BINW (256.0f / 12.0f)
#define MAXPTS 16384
#define RED_CTAS 64
#define RED_THREADS 256

__device__ float4 g_sorted[2][MAXPTS];
__device__ int    g_bincnt[2][BINS];
__device__ int    g_binstart[2][BINS + 1];
__device__ int    g_curs[2][BINS];
__device__ float  g_dist[2 * MAXPTS];
__device__ float  g_part[RED_CTAS];

__device__ __forceinline__ int xbin(float x) {
    int b = (int)((x - GRID_LO) * INV_BINW);
    return min(max(b, 0), BINS - 1);
}

// ---------- 1. zero bin counts ----------
__global__ void zero_kernel() {
    ((int*)g_bincnt)[threadIdx.x] = 0;   // 512 threads
}

// ---------- 2. histogram by x ----------
__global__ void hist_kernel(const float* __restrict__ A,
                            const float* __restrict__ B, int N, int M) {
    int gid = blockIdx.x * blockDim.x + threadIdx.x;
    if (gid >= N + M) return;
    int cl = (gid >= N);
    int i = cl ? gid - N : gid;
    const float* src = cl ? B : A;
    atomicAdd(&g_bincnt[cl][xbin(src[3 * i])], 1);
}

// ---------- 3. exclusive scan over bins (both clouds, one CTA) ----------
__global__ void __launch_bounds__(512)
scan_kernel() {
    __shared__ int s[512];
    const int tid = threadIdx.x;
    const int cl = tid >> 8, b = tid & 255;
    const int cnt = g_bincnt[cl][b];
    s[tid] = cnt;
    __syncthreads();
    #pragma unroll
    for (int off = 1; off < 256; off <<= 1) {
        int v = (b >= off) ? s[tid - off] : 0;
        __syncthreads();
        s[tid] += v;
        __syncthreads();
    }
    const int incl = s[tid];
    g_binstart[cl][b] = incl - cnt;
    g_curs[cl][b] = incl - cnt;
    if (b == 255) g_binstart[cl][256] = incl;
}

// ---------- 4. scatter into x-sorted order (orig index in .w) ----------
__global__ void scatter_kernel(const float* __restrict__ A,
                               const float* __restrict__ B, int N, int M) {
    int gid = blockIdx.x * blockDim.x + threadIdx.x;
    if (gid >= N + M) return;
    int cl = (gid >= N);
    int i = cl ? gid - N : gid;
    const float* src = cl ? B : A;
    float x = src[3 * i], y = src[3 * i + 1], z = src[3 * i + 2];
    int pos = atomicAdd(&g_curs[cl][xbin(x)], 1);
    g_sorted[cl][pos] = make_float4(x, y, z, __int_as_float(i));
}

// ---------- 5. exact two-scan NN, one warp per query ----------
__global__ void __launch_bounds__(256)
query_kernel(int N, int M) {
    const int gw = (blockIdx.x * blockDim.x + threadIdx.x) >> 5;
    const int lane = threadIdx.x & 31;
    if (gw >= N + M) return;
    const int cl = (gw >= N);
    const int i = cl ? gw - N : gw;
    const int ct = 1 - cl;

    const float4 p = g_sorted[cl][i];     // broadcast load
    const float qx = p.x, qy = p.y, qz = p.z;
    const int* __restrict__ bs = g_binstart[ct];
    const float4* __restrict__ pts = g_sorted[ct];
    const int b = xbin(qx);

    // seed: expand until a non-empty bin range (warp-uniform, usually rad=0)
    int s, e, rad = 0;
    for (;;) {
        s = bs[max(b - rad, 0)];
        e = bs[min(b + rad, BINS - 1) + 1];
        if (e > s) break;
        rad++;
    }
    float best = CUDART_INF_F;
    for (int k = s + lane; k < e; k += 32) {
        float4 t = pts[k];
        float dx = qx - t.x, dy = qy - t.y, dz = qz - t.z;
        best = fminf(best, fmaf(dx, dx, fmaf(dy, dy, dz * dz)));
    }
    #pragma unroll
    for (int o = 16; o > 0; o >>= 1)
        best = fminf(best, __shfl_xor_sync(0xFFFFFFFFu, best, o));

    // exact window: every target with |tx-qx| <= d0 is inside [bl, bh]
    // (xbin monotone + consistent clamping; +-1 bin pad for fp safety)
    const float d0 = sqrtf(best);
    const int bl = max(xbin(qx - d0) - 1, 0);
    const int bh = min(xbin(qx + d0) + 1, BINS - 1);
    const int s2 = bs[bl];
    const int e2 = bs[bh + 1];
    if (s2 < s || e2 > e) {               // anything not already scanned?
        for (int k = s2 + lane; k < e2; k += 32) {
            float4 t = pts[k];
            float dx = qx - t.x, dy = qy - t.y, dz = qz - t.z;
            best = fminf(best, fmaf(dx, dx, fmaf(dy, dy, dz * dz)));
        }
        #pragma unroll
        for (int o = 16; o > 0; o >>= 1)
            best = fminf(best, __shfl_xor_sync(0xFFFFFFFFu, best, o));
    }

    if (lane == 0)
        g_dist[(cl ? N : 0) + __float_as_int(p.w)] = sqrtf(best);
}

// ---------- 6-7. deterministic two-stage sum ----------
__global__ void __launch_bounds__(RED_THREADS)
reduce1_kernel(int total) {
    __shared__ float ssum[RED_THREADS / 32];
    const int per = (total + RED_CTAS - 1) / RED_CTAS;
    const int base = blockIdx.x * per;
    const int end = min(base + per, total);

    float acc = 0.0f;
    for (int i = base + threadIdx.x; i < end; i += RED_THREADS)
        acc += g_dist[i];
    #pragma unroll
    for (int o = 16; o > 0; o >>= 1)
        acc += __shfl_down_sync(0xFFFFFFFFu, acc, o);
    if ((threadIdx.x & 31) == 0) ssum[threadIdx.x >> 5] = acc;
    __syncthreads();
    if (threadIdx.x == 0) {
        float v = 0.0f;
        #pragma unroll
        for (int w = 0; w < RED_THREADS / 32; w++) v += ssum[w];
        g_part[blockIdx.x] = v;
    }
}

__global__ void reduce2_kernel(float* __restrict__ out) {
    float acc = 0.0f;
    #pragma unroll
    for (int k = 0; k < RED_CTAS / 32; k++)
        acc += g_part[threadIdx.x + 32 * k];
    #pragma unroll
    for (int o = 16; o > 0; o >>= 1)
        acc += __shfl_down_sync(0xFFFFFFFFu, acc, o);
    if (threadIdx.x == 0) out[0] = acc * 0.001f;
}

extern "C" void kernel_launch(void* const* d_in, const int* in_sizes, int n_in,
                              void* d_out, int out_size)
{
    const float* A = (const float*)d_in[0];   // target_pc [N,3]
    const float* B = (const float*)d_in[1];   // output_pc [M,3]
    const int N = in_sizes[0] / 3;
    const int M = in_sizes[1] / 3;
    const int total = N + M;

    zero_kernel<<<1, 512>>>();
    hist_kernel<<<(total + 255) / 256, 256>>>(A, B, N, M);
    scan_kernel<<<1, 512>>>();
    scatter_kernel<<<(total + 255) / 256, 256>>>(A, B, N, M);
    query_kernel<<<(total * 32 + 255) / 256, 256>>>(N, M);   // warp / query
    reduce1_kernel<<<RED_CTAS, RED_THREADS>>>(total);
    reduce2_kernel<<<1, 32>>>((float*)d_out);
}